// round 15
// baseline (speedup 1.0000x reference)
#include <cuda_runtime.h>
#include <cuda_fp16.h>
#include <cstdint>

// VectorQuantizerRestart: z [16,128,4096] fp32, codebook [1024,128] fp32
#define D_DIM 128
#define T_DIM 4096
#define K_DIM 1024
#define N_TOK 65536

__device__ __align__(16) float g_cnorm[K_DIM];
// split-K candidates: [half 2][token]
__device__ float g_cv[2 * N_TOK];
__device__ int   g_ci[2 * N_TOK];
// per-tile completion counters (zeroed by pre-kernel every launch)
__device__ int   g_cnt[512];
// fp16 2-limb codebook, fragment-ordered:
// [half2][chunk4][s8][limb2][ntp8][lane32][q4] uint32(f16x2)  (512 KB)
__device__ __align__(16) uint32_t g_bfrag[2 * 4 * 8 * 2 * 8 * 32 * 4];

__device__ __forceinline__ void split2(float x, unsigned short& h, unsigned short& m) {
    __half hh = __float2half_rn(x);
    float r = x - __half2float(hh);
    __half mm = __float2half_rn(r);
    h = __half_as_ushort(hh);
    m = __half_as_ushort(mm);
}

__device__ __forceinline__ void mma_f16(float* d, const uint32_t* a, const uint32_t* b) {
    asm volatile(
        "mma.sync.aligned.m16n8k16.row.col.f32.f16.f16.f32 "
        "{%0,%1,%2,%3}, {%4,%5,%6,%7}, {%8,%9}, {%0,%1,%2,%3};"
        : "+f"(d[0]), "+f"(d[1]), "+f"(d[2]), "+f"(d[3])
        : "r"(a[0]), "r"(a[1]), "r"(a[2]), "r"(a[3]), "r"(b[0]), "r"(b[1]));
}

// ---------------------------------------------------------------------------
// Fused pre-kernel: blocks [0,512) = B-frag split, [512,640) = cnorm + cnt-zero.
// ---------------------------------------------------------------------------
__global__ void vq_pre_kernel(const float* __restrict__ cb) {
    int blk = blockIdx.x;
    int tid = threadIdx.x;

    if (blk < 512) {
        // ---- B-frag: codebook -> 2 fp16 limbs, m16n8k16 fragment order
        int e = blk * 256 + tid;               // 131072
        int q    = e & 3;
        int lane = (e >> 2) & 31;
        int ntp  = (e >> 7) & 7;
        int limb = (e >> 10) & 1;
        int s    = (e >> 11) & 7;
        int chunk= (e >> 14) & 3;
        int half = (e >> 16) & 1;
        int n = half * 512 + chunk * 128 + (ntp * 2 + (q >> 1)) * 8 + (lane >> 2);
        int k = s * 16 + ((q & 1) << 3) + (lane & 3) * 2;
        float x0 = cb[n * D_DIM + k];
        float x1 = cb[n * D_DIM + k + 1];
        unsigned short h0, m0, h1, m1;
        split2(x0, h0, m0);
        split2(x1, h1, m1);
        unsigned short lo = (limb == 0) ? h0 : m0;
        unsigned short hi = (limb == 0) ? h1 : m1;
        g_bfrag[e] = (uint32_t)lo | ((uint32_t)hi << 16);
    } else {
        int idx = (blk - 512) * 256 + tid;
        if (idx < 512) g_cnt[idx] = 0;         // reset per-tile counters (every launch)
        // ---- cnorm: one warp per code
        int w    = idx >> 5;
        int lane = tid & 31;
        if (w >= K_DIM) return;
        float s = 0.f;
        #pragma unroll
        for (int d = lane; d < D_DIM; d += 32) {
            float v = cb[(size_t)w * D_DIM + d];
            s = fmaf(v, v, s);
        }
        #pragma unroll
        for (int o = 16; o > 0; o >>= 1) s += __shfl_xor_sync(0xffffffffu, s, o);
        if (lane == 0) g_cnorm[w] = s;
    }
}

// ---------------------------------------------------------------------------
// Kernel 2: 3-term fp16 2-limb mma.sync + register argmin, split-K over codes,
// WITH FUSED GATHER: the second-finishing CTA of each tile (per-tile atomic)
// merges both halves' candidates and writes the quantized output for its 128
// tokens — the standalone gather kernel is gone.
// grid = 1024: blockIdx = tile*2 + half; CTA = 512 codes in 4 chunks of 128.
// CTA: 512 thr = 16 warps = 8 mg x 2 ng; warp tile m16 x n64 (R10 config).
// A (64KB) resident; B double-buffered (2 x 64KB), single-sync pipeline.
// ---------------------------------------------------------------------------
#define A_U4   4096            // uint4: [s8][mt8][limb2][lane32]
#define B_U4   4096            // per buffer: [s8][limb2][ntp8][lane32]
#define SMEM_BYTES ((A_U4 + 2 * B_U4) * 16 + 512 * 4)   // 198656
#define GPAD   129             // gather transpose pad: conflict-free both phases

__global__ __launch_bounds__(512, 1)
void vq_argmin_kernel(const float* __restrict__ z, const float* __restrict__ cb,
                      float* __restrict__ out) {
    extern __shared__ uint4 smem4[];
    uint4* As = smem4;
    uint4* Bs = smem4 + A_U4;
    float* cn = reinterpret_cast<float*>(smem4 + A_U4 + 2 * B_U4);

    const int tid  = threadIdx.x;
    const int lane = tid & 31;
    const int w    = tid >> 5;
    const int mg   = w >> 1;                 // 0..7  (m16 tile)
    const int ng   = w & 1;                  // 0..1  (n64 tile)

    const int tile = blockIdx.x >> 1;
    const int half = blockIdx.x & 1;
    const int n0 = tile * 128;
    const int kb0 = half * 512;
    const int bb = n0 >> 12;
    const int t0 = n0 & (T_DIM - 1);
    const float* zb = z + (size_t)bb * D_DIM * T_DIM + t0;

    const uint32_t bsm = (uint32_t)__cvta_generic_to_shared(Bs);
    const uint32_t cnsm = (uint32_t)__cvta_generic_to_shared(cn);
    const float4*  bsrc = reinterpret_cast<const float4*>(g_bfrag) + half * 4 * B_U4;

    // ---- group 0: cn (2KB) + B chunk 0 (64KB) — overlaps the A-split below
    if (tid < 128) {
        asm volatile("cp.async.ca.shared.global [%0], [%1], 16;"
                     :: "r"(cnsm + tid * 16u), "l"(g_cnorm + kb0 + tid * 4) : "memory");
    }
    #pragma unroll
    for (int i = 0; i < 8; ++i) {
        int e = i * 512 + tid;
        asm volatile("cp.async.cg.shared.global [%0], [%1], 16;"
                     :: "r"(bsm + (uint32_t)e * 16u), "l"(bsrc + e) : "memory");
    }
    asm volatile("cp.async.commit_group;" ::: "memory");

    // ---- A prologue: z -> 2 fp16 limbs in m16n8k16 fragment order.
    for (int p = w; p < 64; p += 16) {
        int s  = p >> 3;
        int mt = p & 7;
        int m = mt * 16 + (lane >> 2);
        int k = s * 16 + (lane & 3) * 2;
        float xv[8];
        xv[0] = zb[(k    ) * T_DIM + m    ];  xv[1] = zb[(k + 1) * T_DIM + m    ];
        xv[2] = zb[(k    ) * T_DIM + m + 8];  xv[3] = zb[(k + 1) * T_DIM + m + 8];
        xv[4] = zb[(k + 8) * T_DIM + m    ];  xv[5] = zb[(k + 9) * T_DIM + m    ];
        xv[6] = zb[(k + 8) * T_DIM + m + 8];  xv[7] = zb[(k + 9) * T_DIM + m + 8];
        unsigned short hh[8], mm[8];
        #pragma unroll
        for (int i = 0; i < 8; i++) split2(xv[i], hh[i], mm[i]);
        #pragma unroll
        for (int limb = 0; limb < 2; limb++) {
            const unsigned short* u = (limb == 0) ? hh : mm;
            uint4 v;
            v.x = (uint32_t)u[0] | ((uint32_t)u[1] << 16);
            v.y = (uint32_t)u[2] | ((uint32_t)u[3] << 16);
            v.z = (uint32_t)u[4] | ((uint32_t)u[5] << 16);
            v.w = (uint32_t)u[6] | ((uint32_t)u[7] << 16);
            As[((s * 8 + mt) * 2 + limb) * 32 + lane] = v;
        }
    }

    float minv[2];
    int   mini[2];
    minv[0] = minv[1] = 3.4e38f;
    mini[0] = mini[1] = 0;

    static const int TLA[3] = {0, 0, 1};
    static const int TLB[3] = {0, 1, 0};

    #pragma unroll 1
    for (int c = 0; c < 4; ++c) {
        asm volatile("cp.async.wait_group 0;" ::: "memory");
        __syncthreads();     // buf[c&1]+A(+cn) visible; all done reading buf[(c+1)&1]

        if (c < 3) {         // prefetch c+1 into the buffer just freed
            int buf1 = (c + 1) & 1;
            const float4* src = bsrc + (c + 1) * B_U4;
            #pragma unroll
            for (int i = 0; i < 8; ++i) {
                int e = i * 512 + tid;
                asm volatile("cp.async.cg.shared.global [%0], [%1], 16;"
                             :: "r"(bsm + (uint32_t)(buf1 * B_U4 + e) * 16u),
                                "l"(src + e) : "memory");
            }
            asm volatile("cp.async.commit_group;" ::: "memory");
        }

        const uint4* Bb = Bs + (c & 1) * B_U4;
        float acc[8][4];
        #pragma unroll
        for (int nt = 0; nt < 8; nt++)
            #pragma unroll
            for (int qi = 0; qi < 4; qi++) acc[nt][qi] = 0.f;

        #pragma unroll
        for (int s = 0; s < 8; ++s) {
            uint32_t afr[2][4];
            #pragma unroll
            for (int limb = 0; limb < 2; limb++) {
                uint4 v = As[((s * 8 + mg) * 2 + limb) * 32 + lane];
                afr[limb][0] = v.x; afr[limb][1] = v.y;
                afr[limb][2] = v.z; afr[limb][3] = v.w;
            }
            uint32_t bfr[2][8][2];            // [limb][ntile][2 regs]
            #pragma unroll
            for (int limb = 0; limb < 2; limb++)
                #pragma unroll
                for (int np = 0; np < 4; np++) {
                    uint4 v = Bb[((s * 2 + limb) * 8 + ng * 4 + np) * 32 + lane];
                    bfr[limb][np * 2    ][0] = v.x; bfr[limb][np * 2    ][1] = v.y;
                    bfr[limb][np * 2 + 1][0] = v.z; bfr[limb][np * 2 + 1][1] = v.w;
                }
            // 3 terms: h*h, h*m, m*h (m*m ~ 2^-22 rel: negligible)
            #pragma unroll
            for (int term = 0; term < 3; term++) {
                const int la = TLA[term], lb = TLB[term];
                #pragma unroll
                for (int nt = 0; nt < 8; nt++)
                    mma_f16(acc[nt], afr[la], bfr[lb][nt]);
            }
        }

        // ---- epilogue: d2 = ||c||^2 - 2*dot, strict-< running min (n ascending)
        #pragma unroll
        for (int nt = 0; nt < 8; nt++) {
            int nl = c * 128 + ng * 64 + nt * 8 + 2 * (lane & 3);
            float cv0 = cn[nl], cv1 = cn[nl + 1];
            int n = kb0 + nl;
            float d00 = fmaf(-2.f, acc[nt][0], cv0);
            float d01 = fmaf(-2.f, acc[nt][1], cv1);
            float d10 = fmaf(-2.f, acc[nt][2], cv0);
            float d11 = fmaf(-2.f, acc[nt][3], cv1);
            if (d00 < minv[0]) { minv[0] = d00; mini[0] = n; }
            if (d01 < minv[0]) { minv[0] = d01; mini[0] = n + 1; }
            if (d10 < minv[1]) { minv[1] = d10; mini[1] = n; }
            if (d11 < minv[1]) { minv[1] = d11; mini[1] = n + 1; }
        }
    }

    // ---- cross-thread reduce: 8 candidates per token -> g_cv/g_ci[half]
    __syncthreads();                          // all compute done before smem reuse
    float* rv = reinterpret_cast<float*>(smem4);          // [128][8]
    int*   ri = reinterpret_cast<int*>(rv + 1024);
    #pragma unroll
    for (int rh = 0; rh < 2; rh++) {
        int tok  = mg * 16 + rh * 8 + (lane >> 2);
        int slot = ng * 4 + (lane & 3);
        rv[tok * 8 + slot] = minv[rh];
        ri[tok * 8 + slot] = mini[rh];
    }
    __syncthreads();
    if (tid < 128) {
        float bv = rv[tid * 8];
        int   bi = ri[tid * 8];
        #pragma unroll
        for (int x = 1; x < 8; x++) {
            float v = rv[tid * 8 + x];
            int   k = ri[tid * 8 + x];
            if (v < bv || (v == bv && k < bi)) { bv = v; bi = k; }
        }
        g_cv[half * N_TOK + n0 + tid] = bv;
        g_ci[half * N_TOK + n0 + tid] = bi;
        __threadfence();                      // publish before signaling
    }
    __syncthreads();

    // ---- per-tile completion: second finisher gathers
    __shared__ int doG;
    if (tid == 0) doG = (atomicAdd(&g_cnt[tile], 1) == 1);
    __syncthreads();
    if (doG == 0) return;

    // ---- fused gather for tokens n0..n0+127 (both halves visible via fence+atomic)
    float* zt   = reinterpret_cast<float*>(smem4);        // [128][GPAD] = 66048 B
    int*   ridx = reinterpret_cast<int*>(zt + 128 * GPAD);
    if (tid < 128) {
        int tg = n0 + tid;
        float v0 = __ldcg(g_cv + tg), v1 = __ldcg(g_cv + N_TOK + tg);
        int   i0 = __ldcg(g_ci + tg), i1 = __ldcg(g_ci + N_TOK + tg);
        ridx[tid] = (v1 < v0) ? i1 : i0;      // half0 wins ties (lower indices)
    }
    __syncthreads();

    // phase 1: warp w loads rows w*8..w*8+7; scalar d = lane+32q:
    // LDG 128B-coalesced, STS banks (tt+lane) conflict-free.
    #pragma unroll
    for (int j = 0; j < 8; ++j) {
        int tt = w * 8 + j;
        const float* src = cb + (size_t)ridx[tt] * D_DIM;
        #pragma unroll
        for (int q = 0; q < 4; ++q) {
            int d = lane + q * 32;
            zt[tt * GPAD + d] = __ldg(src + d);
        }
    }
    __syncthreads();

    // phase 2: warp-fixed d, tt = lane+32j: LDS banks (lane+d) conflict-free,
    // STG 128B-coalesced per instruction.
    #pragma unroll
    for (int i = 0; i < 8; ++i) {
        int d = i * 16 + w;
        size_t obase = ((size_t)(bb * D_DIM + d)) * T_DIM + t0;
        #pragma unroll
        for (int j = 0; j < 4; ++j) {
            int tt = lane + 32 * j;
            out[obase + tt] = zt[tt * GPAD + d];
        }
    }
}

// ---------------------------------------------------------------------------
extern "C" void kernel_launch(void* const* d_in, const int* in_sizes, int n_in,
                              void* d_out, int out_size) {
    const float* z  = (const float*)d_in[0];
    const float* cb = (const float*)d_in[1];
    float* out = (float*)d_out;

    cudaFuncSetAttribute(vq_argmin_kernel,
                         cudaFuncAttributeMaxDynamicSharedMemorySize, SMEM_BYTES);

    vq_pre_kernel<<<640, 256>>>(cb);
    vq_argmin_kernel<<<(N_TOK / 128) * 2, 512, SMEM_BYTES>>>(z, cb, out);
}

// round 16
// speedup vs baseline: 1.1412x; 1.1412x over previous
#include <cuda_runtime.h>
#include <cuda_fp16.h>
#include <cstdint>

// VectorQuantizerRestart: z [16,128,4096] fp32, codebook [1024,128] fp32
#define D_DIM 128
#define T_DIM 4096
#define K_DIM 1024
#define N_TOK 65536

__device__ __align__(16) float g_cnorm[K_DIM];
// split-K candidates: [half 2][token]
__device__ float g_cv[2 * N_TOK];
__device__ int   g_ci[2 * N_TOK];
// fp16 2-limb codebook, fragment-ordered:
// [half2][chunk8][s8][limb2][ntp4][lane32][q4] uint32(f16x2)  (512 KB)
__device__ __align__(16) uint32_t g_bfrag[2 * 8 * 8 * 2 * 4 * 32 * 4];

__device__ __forceinline__ void split2(float x, unsigned short& h, unsigned short& m) {
    __half hh = __float2half_rn(x);
    float r = x - __half2float(hh);
    __half mm = __float2half_rn(r);
    h = __half_as_ushort(hh);
    m = __half_as_ushort(mm);
}

__device__ __forceinline__ void mma_f16(float* d, const uint32_t* a, const uint32_t* b) {
    asm volatile(
        "mma.sync.aligned.m16n8k16.row.col.f32.f16.f16.f32 "
        "{%0,%1,%2,%3}, {%4,%5,%6,%7}, {%8,%9}, {%0,%1,%2,%3};"
        : "+f"(d[0]), "+f"(d[1]), "+f"(d[2]), "+f"(d[3])
        : "r"(a[0]), "r"(a[1]), "r"(a[2]), "r"(a[3]), "r"(b[0]), "r"(b[1]));
}

// ---------------------------------------------------------------------------
// Fused pre-kernel: blocks [0,512) = B-frag split, [512,640) = codebook norms.
// ---------------------------------------------------------------------------
__global__ void vq_pre_kernel(const float* __restrict__ cb) {
    int blk = blockIdx.x;
    int tid = threadIdx.x;

    if (blk < 512) {
        // ---- B-frag: codebook -> 2 fp16 limbs, m16n8k16 fragment order
        // e = [half][chunk8][s][limb][ntp4][lane][q]
        int e = blk * 256 + tid;               // 131072
        int q    = e & 3;
        int lane = (e >> 2) & 31;
        int ntp  = (e >> 7) & 3;
        int limb = (e >> 9) & 1;
        int s    = (e >> 10) & 7;
        int chunk= (e >> 13) & 7;
        int half = (e >> 16) & 1;
        int n = half * 512 + chunk * 64 + (ntp * 2 + (q >> 1)) * 8 + (lane >> 2);
        int k = s * 16 + ((q & 1) << 3) + (lane & 3) * 2;
        float x0 = cb[n * D_DIM + k];
        float x1 = cb[n * D_DIM + k + 1];
        unsigned short h0, m0, h1, m1;
        split2(x0, h0, m0);
        split2(x1, h1, m1);
        unsigned short lo = (limb == 0) ? h0 : m0;
        unsigned short hi = (limb == 0) ? h1 : m1;
        g_bfrag[e] = (uint32_t)lo | ((uint32_t)hi << 16);
    } else {
        // ---- cnorm: one warp per code
        int w    = ((blk - 512) * 256 + tid) >> 5;
        int lane = tid & 31;
        if (w >= K_DIM) return;
        float s = 0.f;
        #pragma unroll
        for (int d = lane; d < D_DIM; d += 32) {
            float v = cb[(size_t)w * D_DIM + d];
            s = fmaf(v, v, s);
        }
        #pragma unroll
        for (int o = 16; o > 0; o >>= 1) s += __shfl_xor_sync(0xffffffffu, s, o);
        if (lane == 0) g_cnorm[w] = s;
    }
}

// ---------------------------------------------------------------------------
// Kernel 2: 3-term fp16 2-limb mma.sync + register argmin, split-K over codes.
// NEW SHAPE FOR OCCUPANCY: tile = 64 tokens, chunk = 64 codes, 8 chunks/CTA.
// SMEM = 98KB -> 2 CTAs/SM -> 8 warps/SMSP (R15 ncu: tensor 48%, occ 25% =>
// latency coverage, not the HMMA wall, is the deficit at 1 CTA/SM).
// grid = 2048: blockIdx = tile*2 + half. CTA: 256 thr = 8 warps = 4mg x 2ng,
// warp tile m16 x n32. A (32KB) resident; B double-buffered (2 x 32KB).
// ---------------------------------------------------------------------------
#define A_U4   2048            // uint4: [s8][mt4][limb2][lane32]
#define B_U4   2048            // per buffer: [s8][limb2][ntp4][lane32]
#define SMEM_BYTES ((A_U4 + 2 * B_U4) * 16 + 512 * 4)   // 100352

__global__ __launch_bounds__(256, 2)
void vq_argmin_kernel(const float* __restrict__ z) {
    extern __shared__ uint4 smem4[];
    uint4* As = smem4;
    uint4* Bs = smem4 + A_U4;
    float* cn = reinterpret_cast<float*>(smem4 + A_U4 + 2 * B_U4);

    const int tid  = threadIdx.x;
    const int lane = tid & 31;
    const int w    = tid >> 5;
    const int mg   = w >> 1;                 // 0..3  (m16 tile)
    const int ng   = w & 1;                  // 0..1  (n32 tile)

    const int tile = blockIdx.x >> 1;        // 0..1023, 64 tokens each
    const int half = blockIdx.x & 1;
    const int n0 = tile * 64;
    const int kb0 = half * 512;
    const int bb = n0 >> 12;
    const int t0 = n0 & (T_DIM - 1);
    const float* zb = z + (size_t)bb * D_DIM * T_DIM + t0;

    const uint32_t bsm = (uint32_t)__cvta_generic_to_shared(Bs);
    const uint32_t cnsm = (uint32_t)__cvta_generic_to_shared(cn);
    const float4*  bsrc = reinterpret_cast<const float4*>(g_bfrag) + half * 8 * B_U4;

    // ---- group 0: cn (2KB) + B chunk 0 (32KB) — overlaps the A-split below
    if (tid < 128) {
        asm volatile("cp.async.ca.shared.global [%0], [%1], 16;"
                     :: "r"(cnsm + tid * 16u), "l"(g_cnorm + kb0 + tid * 4) : "memory");
    }
    #pragma unroll
    for (int i = 0; i < 8; ++i) {
        int e = i * 256 + tid;
        asm volatile("cp.async.cg.shared.global [%0], [%1], 16;"
                     :: "r"(bsm + (uint32_t)e * 16u), "l"(bsrc + e) : "memory");
    }
    asm volatile("cp.async.commit_group;" ::: "memory");

    // ---- A prologue: z -> 2 fp16 limbs in m16n8k16 fragment order (64 tokens).
    for (int p = w; p < 32; p += 8) {
        int s  = p >> 2;
        int mt = p & 3;
        int m = mt * 16 + (lane >> 2);
        int k = s * 16 + (lane & 3) * 2;
        float xv[8];
        xv[0] = zb[(k    ) * T_DIM + m    ];  xv[1] = zb[(k + 1) * T_DIM + m    ];
        xv[2] = zb[(k    ) * T_DIM + m + 8];  xv[3] = zb[(k + 1) * T_DIM + m + 8];
        xv[4] = zb[(k + 8) * T_DIM + m    ];  xv[5] = zb[(k + 9) * T_DIM + m    ];
        xv[6] = zb[(k + 8) * T_DIM + m + 8];  xv[7] = zb[(k + 9) * T_DIM + m + 8];
        unsigned short hh[8], mm[8];
        #pragma unroll
        for (int i = 0; i < 8; i++) split2(xv[i], hh[i], mm[i]);
        #pragma unroll
        for (int limb = 0; limb < 2; limb++) {
            const unsigned short* u = (limb == 0) ? hh : mm;
            uint4 v;
            v.x = (uint32_t)u[0] | ((uint32_t)u[1] << 16);
            v.y = (uint32_t)u[2] | ((uint32_t)u[3] << 16);
            v.z = (uint32_t)u[4] | ((uint32_t)u[5] << 16);
            v.w = (uint32_t)u[6] | ((uint32_t)u[7] << 16);
            As[((s * 4 + mt) * 2 + limb) * 32 + lane] = v;
        }
    }

    float minv[2];
    int   mini[2];
    minv[0] = minv[1] = 3.4e38f;
    mini[0] = mini[1] = 0;

    static const int TLA[3] = {0, 0, 1};
    static const int TLB[3] = {0, 1, 0};

    #pragma unroll 1
    for (int c = 0; c < 8; ++c) {
        asm volatile("cp.async.wait_group 0;" ::: "memory");
        __syncthreads();     // buf[c&1]+A(+cn) visible; all done reading buf[(c+1)&1]

        if (c < 7) {         // prefetch c+1 into the buffer just freed
            int buf1 = (c + 1) & 1;
            const float4* src = bsrc + (c + 1) * B_U4;
            #pragma unroll
            for (int i = 0; i < 8; ++i) {
                int e = i * 256 + tid;
                asm volatile("cp.async.cg.shared.global [%0], [%1], 16;"
                             :: "r"(bsm + (uint32_t)(buf1 * B_U4 + e) * 16u),
                                "l"(src + e) : "memory");
            }
            asm volatile("cp.async.commit_group;" ::: "memory");
        }

        const uint4* Bb = Bs + (c & 1) * B_U4;
        float acc[4][4];                      // [ntile][quad]
        #pragma unroll
        for (int nt = 0; nt < 4; nt++)
            #pragma unroll
            for (int qi = 0; qi < 4; qi++) acc[nt][qi] = 0.f;

        #pragma unroll
        for (int s = 0; s < 8; ++s) {
            uint32_t afr[2][4];
            #pragma unroll
            for (int limb = 0; limb < 2; limb++) {
                uint4 v = As[((s * 4 + mg) * 2 + limb) * 32 + lane];
                afr[limb][0] = v.x; afr[limb][1] = v.y;
                afr[limb][2] = v.z; afr[limb][3] = v.w;
            }
            uint32_t bfr[2][4][2];            // [limb][ntile][2 regs]
            #pragma unroll
            for (int limb = 0; limb < 2; limb++)
                #pragma unroll
                for (int np = 0; np < 2; np++) {
                    uint4 v = Bb[((s * 2 + limb) * 4 + ng * 2 + np) * 32 + lane];
                    bfr[limb][np * 2    ][0] = v.x; bfr[limb][np * 2    ][1] = v.y;
                    bfr[limb][np * 2 + 1][0] = v.z; bfr[limb][np * 2 + 1][1] = v.w;
                }
            // 3 terms: h*h, h*m, m*h (m*m ~ 2^-22 rel: negligible)
            #pragma unroll
            for (int term = 0; term < 3; term++) {
                const int la = TLA[term], lb = TLB[term];
                #pragma unroll
                for (int nt = 0; nt < 4; nt++)
                    mma_f16(acc[nt], afr[la], bfr[lb][nt]);
            }
        }

        // ---- epilogue: d2 = ||c||^2 - 2*dot, strict-< running min (n ascending)
        #pragma unroll
        for (int nt = 0; nt < 4; nt++) {
            int nl = c * 64 + ng * 32 + nt * 8 + 2 * (lane & 3);
            float cv0 = cn[nl], cv1 = cn[nl + 1];
            int n = kb0 + nl;
            float d00 = fmaf(-2.f, acc[nt][0], cv0);
            float d01 = fmaf(-2.f, acc[nt][1], cv1);
            float d10 = fmaf(-2.f, acc[nt][2], cv0);
            float d11 = fmaf(-2.f, acc[nt][3], cv1);
            if (d00 < minv[0]) { minv[0] = d00; mini[0] = n; }
            if (d01 < minv[0]) { minv[0] = d01; mini[0] = n + 1; }
            if (d10 < minv[1]) { minv[1] = d10; mini[1] = n; }
            if (d11 < minv[1]) { minv[1] = d11; mini[1] = n + 1; }
        }
    }

    // ---- cross-thread reduce: 8 candidates per token -> g_cv/g_ci[half]
    __syncthreads();                          // all compute done before smem reuse
    float* rv = reinterpret_cast<float*>(smem4);          // [64][8]
    int*   ri = reinterpret_cast<int*>(rv + 512);
    #pragma unroll
    for (int rh = 0; rh < 2; rh++) {
        int tok  = mg * 16 + rh * 8 + (lane >> 2);
        int slot = ng * 4 + (lane & 3);
        rv[tok * 8 + slot] = minv[rh];
        ri[tok * 8 + slot] = mini[rh];
    }
    __syncthreads();
    if (tid < 64) {
        float bv = rv[tid * 8];
        int   bi = ri[tid * 8];
        #pragma unroll
        for (int x = 1; x < 8; x++) {
            float v = rv[tid * 8 + x];
            int   k = ri[tid * 8 + x];
            if (v < bv || (v == bv && k < bi)) { bv = v; bi = k; }
        }
        g_cv[half * N_TOK + n0 + tid] = bv;
        g_ci[half * N_TOK + n0 + tid] = bi;
    }
}

// ---------------------------------------------------------------------------
// Kernel 3: gather, smem-transpose (R14 — best measured). Block = 32 tokens.
// half0 indices < half1, so half0 wins ties (first-min semantics).
// ---------------------------------------------------------------------------
#define GPAD 133
__global__ __launch_bounds__(256, 4)
void vq_gather_kernel(const float* __restrict__ cb, float* __restrict__ out) {
    __shared__ float zt[32 * GPAD];
    __shared__ int   ridx[32];

    const int tid  = threadIdx.x;
    const int lane = tid & 31;
    const int wp   = tid >> 5;
    const int tg0  = blockIdx.x * 32;
    const int b    = tg0 >> 12;
    const int t0   = tg0 & (T_DIM - 1);

    if (tid < 32) {
        int tg = tg0 + tid;
        float v0 = g_cv[tg], v1 = g_cv[N_TOK + tg];
        ridx[tid] = (v1 < v0) ? g_ci[N_TOK + tg] : g_ci[tg];
    }
    __syncthreads();

    #pragma unroll
    for (int j = 0; j < 4; ++j) {
        int tt = wp * 4 + j;
        const float4* src = reinterpret_cast<const float4*>(
            cb + (size_t)ridx[tt] * D_DIM) + lane;
        float4 v = __ldg(src);
        float* dst = zt + tt * GPAD + lane * 4;
        dst[0] = v.x; dst[1] = v.y; dst[2] = v.z; dst[3] = v.w;
    }
    __syncthreads();

    #pragma unroll
    for (int i = 0; i < 4; ++i) {
        int e = i * 256 + tid;
        int d = e >> 3;
        int g = e & 7;
        float4 v;
        v.x = zt[(g * 4 + 0) * GPAD + d];
        v.y = zt[(g * 4 + 1) * GPAD + d];
        v.z = zt[(g * 4 + 2) * GPAD + d];
        v.w = zt[(g * 4 + 3) * GPAD + d];
        size_t o = ((size_t)(b * D_DIM + d)) * T_DIM + t0 + g * 4;
        *reinterpret_cast<float4*>(out + o) = v;
    }
}

// ---------------------------------------------------------------------------
extern "C" void kernel_launch(void* const* d_in, const int* in_sizes, int n_in,
                              void* d_out, int out_size) {
    const float* z  = (const float*)d_in[0];
    const float* cb = (const float*)d_in[1];
    float* out = (float*)d_out;

    cudaFuncSetAttribute(vq_argmin_kernel,
                         cudaFuncAttributeMaxDynamicSharedMemorySize, SMEM_BYTES);

    vq_pre_kernel<<<640, 256>>>(cb);
    vq_argmin_kernel<<<(N_TOK / 64) * 2, 256, SMEM_BYTES>>>(z);
    vq_gather_kernel<<<N_TOK / 32, 256>>>(cb, out);
}

// round 17
// speedup vs baseline: 1.1567x; 1.0136x over previous
#include <cuda_runtime.h>
#include <cuda_fp16.h>
#include <cstdint>

// VectorQuantizerRestart: z [16,128,4096] fp32, codebook [1024,128] fp32
#define D_DIM 128
#define T_DIM 4096
#define K_DIM 1024
#define N_TOK 65536

__device__ __align__(16) float g_cnorm[K_DIM];
// split-K candidates: [half 2][token]
__device__ float g_cv[2 * N_TOK];
__device__ int   g_ci[2 * N_TOK];
// fp16 2-limb codebook, fragment-ordered:
// [half2][chunk4][s8][limb2][ntp8][lane32][q4] uint32(f16x2)  (512 KB)
__device__ __align__(16) uint32_t g_bfrag[2 * 4 * 8 * 2 * 8 * 32 * 4];

__device__ __forceinline__ void split2(float x, unsigned short& h, unsigned short& m) {
    __half hh = __float2half_rn(x);
    float r = x - __half2float(hh);
    __half mm = __float2half_rn(r);
    h = __half_as_ushort(hh);
    m = __half_as_ushort(mm);
}

__device__ __forceinline__ void mma_f16(float* d, const uint32_t* a, const uint32_t* b) {
    asm volatile(
        "mma.sync.aligned.m16n8k16.row.col.f32.f16.f16.f32 "
        "{%0,%1,%2,%3}, {%4,%5,%6,%7}, {%8,%9}, {%0,%1,%2,%3};"
        : "+f"(d[0]), "+f"(d[1]), "+f"(d[2]), "+f"(d[3])
        : "r"(a[0]), "r"(a[1]), "r"(a[2]), "r"(a[3]), "r"(b[0]), "r"(b[1]));
}

// ---------------------------------------------------------------------------
// Fused pre-kernel: blocks [0,512) = B-frag split, [512,640) = codebook norms.
// ---------------------------------------------------------------------------
__global__ void vq_pre_kernel(const float* __restrict__ cb) {
    int blk = blockIdx.x;
    int tid = threadIdx.x;

    if (blk < 512) {
        // ---- B-frag: codebook -> 2 fp16 limbs, m16n8k16 fragment order
        int e = blk * 256 + tid;               // 131072
        int q    = e & 3;
        int lane = (e >> 2) & 31;
        int ntp  = (e >> 7) & 7;
        int limb = (e >> 10) & 1;
        int s    = (e >> 11) & 7;
        int chunk= (e >> 14) & 3;
        int half = (e >> 16) & 1;
        int n = half * 512 + chunk * 128 + (ntp * 2 + (q >> 1)) * 8 + (lane >> 2);
        int k = s * 16 + ((q & 1) << 3) + (lane & 3) * 2;
        float x0 = cb[n * D_DIM + k];
        float x1 = cb[n * D_DIM + k + 1];
        unsigned short h0, m0, h1, m1;
        split2(x0, h0, m0);
        split2(x1, h1, m1);
        unsigned short lo = (limb == 0) ? h0 : m0;
        unsigned short hi = (limb == 0) ? h1 : m1;
        g_bfrag[e] = (uint32_t)lo | ((uint32_t)hi << 16);
    } else {
        // ---- cnorm: one warp per code
        int w    = ((blk - 512) * 256 + tid) >> 5;
        int lane = tid & 31;
        if (w >= K_DIM) return;
        float s = 0.f;
        #pragma unroll
        for (int d = lane; d < D_DIM; d += 32) {
            float v = cb[(size_t)w * D_DIM + d];
            s = fmaf(v, v, s);
        }
        #pragma unroll
        for (int o = 16; o > 0; o >>= 1) s += __shfl_xor_sync(0xffffffffu, s, o);
        if (lane == 0) g_cnorm[w] = s;
    }
}

// ---------------------------------------------------------------------------
// Kernel 2 (R14/R10 config — session-best argmin, unchanged): 3-term fp16
// 2-limb mma.sync + register argmin, split-K over codes. grid = 1024:
// blockIdx = tile*2 + half; CTA = 512 codes in 4 chunks of 128.
// CTA: 512 thr = 16 warps = 8 mg x 2 ng; warp tile m16 x n64.
// A (64KB) resident; B double-buffered (2 x 64KB), single-sync pipeline.
// ---------------------------------------------------------------------------
#define A_U4   4096            // uint4: [s8][mt8][limb2][lane32]
#define B_U4   4096            // per buffer: [s8][limb2][ntp8][lane32]
#define SMEM_BYTES ((A_U4 + 2 * B_U4) * 16 + 512 * 4)   // 198656

__global__ __launch_bounds__(512, 1)
void vq_argmin_kernel(const float* __restrict__ z) {
    extern __shared__ uint4 smem4[];
    uint4* As = smem4;
    uint4* Bs = smem4 + A_U4;
    float* cn = reinterpret_cast<float*>(smem4 + A_U4 + 2 * B_U4);

    const int tid  = threadIdx.x;
    const int lane = tid & 31;
    const int w    = tid >> 5;
    const int mg   = w >> 1;                 // 0..7  (m16 tile)
    const int ng   = w & 1;                  // 0..1  (n64 tile)

    const int tile = blockIdx.x >> 1;
    const int half = blockIdx.x & 1;
    const int n0 = tile * 128;
    const int kb0 = half * 512;
    const int bb = n0 >> 12;
    const int t0 = n0 & (T_DIM - 1);
    const float* zb = z + (size_t)bb * D_DIM * T_DIM + t0;

    const uint32_t bsm = (uint32_t)__cvta_generic_to_shared(Bs);
    const uint32_t cnsm = (uint32_t)__cvta_generic_to_shared(cn);
    const float4*  bsrc = reinterpret_cast<const float4*>(g_bfrag) + half * 4 * B_U4;

    // ---- group 0: cn (2KB) + B chunk 0 (64KB) — overlaps the A-split below
    if (tid < 128) {
        asm volatile("cp.async.ca.shared.global [%0], [%1], 16;"
                     :: "r"(cnsm + tid * 16u), "l"(g_cnorm + kb0 + tid * 4) : "memory");
    }
    #pragma unroll
    for (int i = 0; i < 8; ++i) {
        int e = i * 512 + tid;
        asm volatile("cp.async.cg.shared.global [%0], [%1], 16;"
                     :: "r"(bsm + (uint32_t)e * 16u), "l"(bsrc + e) : "memory");
    }
    asm volatile("cp.async.commit_group;" ::: "memory");

    // ---- A prologue: z -> 2 fp16 limbs in m16n8k16 fragment order.
    for (int p = w; p < 64; p += 16) {
        int s  = p >> 3;
        int mt = p & 7;
        int m = mt * 16 + (lane >> 2);
        int k = s * 16 + (lane & 3) * 2;
        float xv[8];
        xv[0] = zb[(k    ) * T_DIM + m    ];  xv[1] = zb[(k + 1) * T_DIM + m    ];
        xv[2] = zb[(k    ) * T_DIM + m + 8];  xv[3] = zb[(k + 1) * T_DIM + m + 8];
        xv[4] = zb[(k + 8) * T_DIM + m    ];  xv[5] = zb[(k + 9) * T_DIM + m    ];
        xv[6] = zb[(k + 8) * T_DIM + m + 8];  xv[7] = zb[(k + 9) * T_DIM + m + 8];
        unsigned short hh[8], mm[8];
        #pragma unroll
        for (int i = 0; i < 8; i++) split2(xv[i], hh[i], mm[i]);
        #pragma unroll
        for (int limb = 0; limb < 2; limb++) {
            const unsigned short* u = (limb == 0) ? hh : mm;
            uint4 v;
            v.x = (uint32_t)u[0] | ((uint32_t)u[1] << 16);
            v.y = (uint32_t)u[2] | ((uint32_t)u[3] << 16);
            v.z = (uint32_t)u[4] | ((uint32_t)u[5] << 16);
            v.w = (uint32_t)u[6] | ((uint32_t)u[7] << 16);
            As[((s * 8 + mt) * 2 + limb) * 32 + lane] = v;
        }
    }

    float minv[2];
    int   mini[2];
    minv[0] = minv[1] = 3.4e38f;
    mini[0] = mini[1] = 0;

    static const int TLA[3] = {0, 0, 1};
    static const int TLB[3] = {0, 1, 0};

    #pragma unroll 1
    for (int c = 0; c < 4; ++c) {
        asm volatile("cp.async.wait_group 0;" ::: "memory");
        __syncthreads();     // buf[c&1]+A(+cn) visible; all done reading buf[(c+1)&1]

        if (c < 3) {         // prefetch c+1 into the buffer just freed
            int buf1 = (c + 1) & 1;
            const float4* src = bsrc + (c + 1) * B_U4;
            #pragma unroll
            for (int i = 0; i < 8; ++i) {
                int e = i * 512 + tid;
                asm volatile("cp.async.cg.shared.global [%0], [%1], 16;"
                             :: "r"(bsm + (uint32_t)(buf1 * B_U4 + e) * 16u),
                                "l"(src + e) : "memory");
            }
            asm volatile("cp.async.commit_group;" ::: "memory");
        }

        const uint4* Bb = Bs + (c & 1) * B_U4;
        float acc[8][4];
        #pragma unroll
        for (int nt = 0; nt < 8; nt++)
            #pragma unroll
            for (int qi = 0; qi < 4; qi++) acc[nt][qi] = 0.f;

        #pragma unroll
        for (int s = 0; s < 8; ++s) {
            uint32_t afr[2][4];
            #pragma unroll
            for (int limb = 0; limb < 2; limb++) {
                uint4 v = As[((s * 8 + mg) * 2 + limb) * 32 + lane];
                afr[limb][0] = v.x; afr[limb][1] = v.y;
                afr[limb][2] = v.z; afr[limb][3] = v.w;
            }
            uint32_t bfr[2][8][2];            // [limb][ntile][2 regs]
            #pragma unroll
            for (int limb = 0; limb < 2; limb++)
                #pragma unroll
                for (int np = 0; np < 4; np++) {
                    uint4 v = Bb[((s * 2 + limb) * 8 + ng * 4 + np) * 32 + lane];
                    bfr[limb][np * 2    ][0] = v.x; bfr[limb][np * 2    ][1] = v.y;
                    bfr[limb][np * 2 + 1][0] = v.z; bfr[limb][np * 2 + 1][1] = v.w;
                }
            // 3 terms: h*h, h*m, m*h (m*m ~ 2^-22 rel: negligible)
            #pragma unroll
            for (int term = 0; term < 3; term++) {
                const int la = TLA[term], lb = TLB[term];
                #pragma unroll
                for (int nt = 0; nt < 8; nt++)
                    mma_f16(acc[nt], afr[la], bfr[lb][nt]);
            }
        }

        // ---- epilogue: d2 = ||c||^2 - 2*dot, strict-< running min (n ascending)
        #pragma unroll
        for (int nt = 0; nt < 8; nt++) {
            int nl = c * 128 + ng * 64 + nt * 8 + 2 * (lane & 3);
            float cv0 = cn[nl], cv1 = cn[nl + 1];
            int n = kb0 + nl;
            float d00 = fmaf(-2.f, acc[nt][0], cv0);
            float d01 = fmaf(-2.f, acc[nt][1], cv1);
            float d10 = fmaf(-2.f, acc[nt][2], cv0);
            float d11 = fmaf(-2.f, acc[nt][3], cv1);
            if (d00 < minv[0]) { minv[0] = d00; mini[0] = n; }
            if (d01 < minv[0]) { minv[0] = d01; mini[0] = n + 1; }
            if (d10 < minv[1]) { minv[1] = d10; mini[1] = n; }
            if (d11 < minv[1]) { minv[1] = d11; mini[1] = n + 1; }
        }
    }

    // ---- cross-thread reduce: 8 candidates per token -> g_cv/g_ci[half]
    __syncthreads();                          // all compute done before smem reuse
    float* rv = reinterpret_cast<float*>(smem4);          // [128][8]
    int*   ri = reinterpret_cast<int*>(rv + 1024);
    #pragma unroll
    for (int rh = 0; rh < 2; rh++) {
        int tok  = mg * 16 + rh * 8 + (lane >> 2);
        int slot = ng * 4 + (lane & 3);
        rv[tok * 8 + slot] = minv[rh];
        ri[tok * 8 + slot] = mini[rh];
    }
    __syncthreads();
    if (tid < 128) {
        float bv = rv[tid * 8];
        int   bi = ri[tid * 8];
        #pragma unroll
        for (int x = 1; x < 8; x++) {
            float v = rv[tid * 8 + x];
            int   k = ri[tid * 8 + x];
            if (v < bv || (v == bv && k < bi)) { bv = v; bi = k; }
        }
        g_cv[half * N_TOK + n0 + tid] = bv;
        g_ci[half * N_TOK + n0 + tid] = bi;
    }
}

// ---------------------------------------------------------------------------
// Kernel 3: gather, conflict-free scalar transpose (R15 pattern, standalone).
// Block = 32 tokens, 256 thr, 16.6KB smem (high occupancy).
// Phase 1: warp wp loads rows wp*4..+3; d = lane+32q: LDG 128B-coalesced,
//          STS banks (tt + lane) mod 32 conflict-free (GPAD=129).
// Phase 2: warp w owns d = i*8 + w, tt = lane: LDS banks (lane + d) mod 32
//          conflict-free; STG 128B-coalesced.
// half0 indices < half1, so half0 wins ties (first-min semantics).
// ---------------------------------------------------------------------------
#define GPAD 129
__global__ __launch_bounds__(256, 6)
void vq_gather_kernel(const float* __restrict__ cb, float* __restrict__ out) {
    __shared__ float zt[32 * GPAD];
    __shared__ int   ridx[32];

    const int tid  = threadIdx.x;
    const int lane = tid & 31;
    const int wp   = tid >> 5;
    const int tg0  = blockIdx.x * 32;
    const int b    = tg0 >> 12;
    const int t0   = tg0 & (T_DIM - 1);

    if (tid < 32) {
        int tg = tg0 + tid;
        float v0 = __ldcg(g_cv + tg), v1 = __ldcg(g_cv + N_TOK + tg);
        int   i0 = __ldcg(g_ci + tg), i1 = __ldcg(g_ci + N_TOK + tg);
        ridx[tid] = (v1 < v0) ? i1 : i0;
    }
    __syncthreads();

    // phase 1
    #pragma unroll
    for (int j = 0; j < 4; ++j) {
        int tt = wp * 4 + j;
        const float* src = cb + (size_t)ridx[tt] * D_DIM;
        #pragma unroll
        for (int q = 0; q < 4; ++q) {
            int d = lane + q * 32;
            zt[tt * GPAD + d] = __ldg(src + d);
        }
    }
    __syncthreads();

    // phase 2
    #pragma unroll
    for (int i = 0; i < 16; ++i) {
        int d = i * 8 + wp;
        out[((size_t)(b * D_DIM + d)) * T_DIM + t0 + lane] = zt[lane * GPAD + d];
    }
}

// ---------------------------------------------------------------------------
extern "C" void kernel_launch(void* const* d_in, const int* in_sizes, int n_in,
                              void* d_out, int out_size) {
    const float* z  = (const float*)d_in[0];
    const float* cb = (const float*)d_in[1];
    float* out = (float*)d_out;

    cudaFuncSetAttribute(vq_argmin_kernel,
                         cudaFuncAttributeMaxDynamicSharedMemorySize, SMEM_BYTES);

    vq_pre_kernel<<<640, 256>>>(cb);
    vq_argmin_kernel<<<(N_TOK / 128) * 2, 512, SMEM_BYTES>>>(z);
    vq_gather_kernel<<<N_TOK / 32, 256>>>(cb, out);
}